// round 7
// baseline (speedup 1.0000x reference)
#include <cuda_runtime.h>
#include <cuda_bf16.h>

// Problem constants (fixed by reference setup_inputs)
#define B_DIM 32
#define HW (1024 * 1024)
#define VEC (HW / 4)          // float4 pixels per image
#define THREADS 256
#define NBLOCKS (VEC / THREADS)   // 1024
#define GROUP 8                   // b-slices batched per load group
#define LAMBDA_F 0.1f

// Global accumulators: [0]=diff2, [1]=G2, [2]=H2. Zero-initialized at module
// load; the finalizing block resets them, so each graph replay starts clean.
__device__ double g_acc[3];
__device__ unsigned int g_done_count;

__global__ __launch_bounds__(THREADS, 3) void pra_fused_kernel(
    const float4* __restrict__ est, const float4* __restrict__ gt,
    float* __restrict__ out)
{
    int p = blockIdx.x * THREADS + threadIdx.x;   // vec-pixel index, p < VEC

    // Per-pixel (x4 lanes) accumulators over the batch dimension:
    //   sd = sum_b (e - g)   (mask: sum_b e > sum_b g  <=>  sd > 0)
    //   e2 = sum_b e^2
    float4 sd = make_float4(0.f, 0.f, 0.f, 0.f);
    float4 e2 = make_float4(0.f, 0.f, 0.f, 0.f);
    float diff2 = 0.f;

    // Front-batch GROUP b-slices of (est, gt) loads before consuming any:
    // 16 independent LDG.128 per thread per iteration -> very deep MLP.
    for (int b0 = 0; b0 < B_DIM; b0 += GROUP) {
        float4 eb[GROUP], gb[GROUP];
        #pragma unroll
        for (int j = 0; j < GROUP; j++)
            eb[j] = est[(size_t)(b0 + j) * VEC + p];
        #pragma unroll
        for (int j = 0; j < GROUP; j++)
            gb[j] = gt[(size_t)(b0 + j) * VEC + p];

        #pragma unroll
        for (int j = 0; j < GROUP; j++) {
            float4 e = eb[j], g = gb[j];
            float dx = e.x - g.x, dy = e.y - g.y, dz = e.z - g.z, dw = e.w - g.w;
            sd.x += dx; sd.y += dy; sd.z += dz; sd.w += dw;
            e2.x = fmaf(e.x, e.x, e2.x);
            e2.y = fmaf(e.y, e.y, e2.y);
            e2.z = fmaf(e.z, e.z, e2.z);
            e2.w = fmaf(e.w, e.w, e2.w);
            diff2 = fmaf(dx, dx, diff2);
            diff2 = fmaf(dy, dy, diff2);
            diff2 = fmaf(dz, dz, diff2);
            diff2 = fmaf(dw, dw, diff2);
        }
    }

    float g2 = e2.x + e2.y + e2.z + e2.w;
    float h2 = (sd.x > 0.f ? e2.x : 0.f)
             + (sd.y > 0.f ? e2.y : 0.f)
             + (sd.z > 0.f ? e2.z : 0.f)
             + (sd.w > 0.f ? e2.w : 0.f);

    // ---- block reduction: warp shuffle then shared ----
    #pragma unroll
    for (int off = 16; off > 0; off >>= 1) {
        diff2 += __shfl_down_sync(0xffffffffu, diff2, off);
        g2    += __shfl_down_sync(0xffffffffu, g2,    off);
        h2    += __shfl_down_sync(0xffffffffu, h2,    off);
    }

    __shared__ float s_d[THREADS / 32];
    __shared__ float s_g[THREADS / 32];
    __shared__ float s_h[THREADS / 32];
    int lane = threadIdx.x & 31;
    int wid  = threadIdx.x >> 5;
    if (lane == 0) { s_d[wid] = diff2; s_g[wid] = g2; s_h[wid] = h2; }
    __syncthreads();

    if (wid == 0) {
        float d  = (lane < THREADS / 32) ? s_d[lane] : 0.f;
        float gg = (lane < THREADS / 32) ? s_g[lane] : 0.f;
        float hh = (lane < THREADS / 32) ? s_h[lane] : 0.f;
        #pragma unroll
        for (int off = 4; off > 0; off >>= 1) {
            d  += __shfl_down_sync(0xffffffffu, d,  off);
            gg += __shfl_down_sync(0xffffffffu, gg, off);
            hh += __shfl_down_sync(0xffffffffu, hh, off);
        }
        if (lane == 0) {
            atomicAdd(&g_acc[0], (double)d);
            atomicAdd(&g_acc[1], (double)gg);
            atomicAdd(&g_acc[2], (double)hh);
            __threadfence();
            unsigned int prev = atomicAdd(&g_done_count, 1u);
            if (prev == NBLOCKS - 1) {
                // Last block: all adds globally visible. Read via atomic path
                // (L2) to avoid stale L1, finalize, reset for next replay.
                double diff2_t = atomicAdd(&g_acc[0], 0.0);
                double g2_t    = atomicAdd(&g_acc[1], 0.0);
                double h2_t    = atomicAdd(&g_acc[2], 0.0);
                out[0] = (float)(diff2_t / g2_t + (double)LAMBDA_F * (diff2_t / h2_t));
                g_acc[0] = 0.0;
                g_acc[1] = 0.0;
                g_acc[2] = 0.0;
                __threadfence();
                g_done_count = 0u;
            }
        }
    }
}

extern "C" void kernel_launch(void* const* d_in, const int* in_sizes, int n_in,
                              void* d_out, int out_size) {
    const float4* est = (const float4*)d_in[0];
    const float4* gt  = (const float4*)d_in[1];
    float* out = (float*)d_out;

    pra_fused_kernel<<<NBLOCKS, THREADS>>>(est, gt, out);
}

// round 8
// speedup vs baseline: 1.0512x; 1.0512x over previous
#include <cuda_runtime.h>
#include <cuda_bf16.h>

// Problem constants (fixed by reference setup_inputs)
#define B_DIM 32
#define HW (1024 * 1024)
#define VEC (HW / 4)              // float4 pixels per image = 262144
#define THREADS 256
#define BLOCKS_PER_SM 4
#define NSM 148
#define NBLOCKS (NSM * BLOCKS_PER_SM)   // 592: exactly one resident wave
#define GROUP 4                          // b-slices batched per load group
#define LAMBDA_F 0.1f

// Global accumulators: [0]=diff2, [1]=G2, [2]=H2. Zero-initialized at module
// load; the finalizing block resets them, so each graph replay starts clean.
__device__ double g_acc[3];
__device__ unsigned int g_done_count;

__global__ __launch_bounds__(THREADS, BLOCKS_PER_SM) void pra_fused_kernel(
    const float4* __restrict__ est, const float4* __restrict__ gt,
    float* __restrict__ out)
{
    // Per-pixel accumulators (x4 lanes), summed over batch:
    //   sd = sum_b (e - g)   (mask: sum_b e > sum_b g  <=>  sd > 0)
    //   e2 = sum_b e^2
    // diff2 accumulates across ALL pixels this thread owns (scalar sum anyway).
    float diff2 = 0.f;
    float g2_acc = 0.f;
    float h2_acc = 0.f;

    const int stride = NBLOCKS * THREADS;   // 151552

    // Grid-stride over pixel columns: every resident block loops until the
    // 262144 float4 columns are covered (threads take 1 or 2 columns).
    for (int p = blockIdx.x * THREADS + threadIdx.x; p < VEC; p += stride) {
        float4 sd = make_float4(0.f, 0.f, 0.f, 0.f);
        float4 e2 = make_float4(0.f, 0.f, 0.f, 0.f);

        // Front-batch GROUP b-slices of (est, gt) loads before consuming:
        // 8 independent LDG.128 per thread per group -> deep MLP (R6 optimum).
        for (int b0 = 0; b0 < B_DIM; b0 += GROUP) {
            float4 eb[GROUP], gb[GROUP];
            #pragma unroll
            for (int j = 0; j < GROUP; j++)
                eb[j] = est[(size_t)(b0 + j) * VEC + p];
            #pragma unroll
            for (int j = 0; j < GROUP; j++)
                gb[j] = gt[(size_t)(b0 + j) * VEC + p];

            #pragma unroll
            for (int j = 0; j < GROUP; j++) {
                float4 e = eb[j], g = gb[j];
                float dx = e.x - g.x, dy = e.y - g.y,
                      dz = e.z - g.z, dw = e.w - g.w;
                sd.x += dx; sd.y += dy; sd.z += dz; sd.w += dw;
                e2.x = fmaf(e.x, e.x, e2.x);
                e2.y = fmaf(e.y, e.y, e2.y);
                e2.z = fmaf(e.z, e.z, e2.z);
                e2.w = fmaf(e.w, e.w, e2.w);
                diff2 = fmaf(dx, dx, diff2);
                diff2 = fmaf(dy, dy, diff2);
                diff2 = fmaf(dz, dz, diff2);
                diff2 = fmaf(dw, dw, diff2);
            }
        }

        g2_acc += e2.x + e2.y + e2.z + e2.w;
        h2_acc += (sd.x > 0.f ? e2.x : 0.f)
                + (sd.y > 0.f ? e2.y : 0.f)
                + (sd.z > 0.f ? e2.z : 0.f)
                + (sd.w > 0.f ? e2.w : 0.f);
    }

    float g2 = g2_acc;
    float h2 = h2_acc;

    // ---- block reduction: warp shuffle then shared ----
    #pragma unroll
    for (int off = 16; off > 0; off >>= 1) {
        diff2 += __shfl_down_sync(0xffffffffu, diff2, off);
        g2    += __shfl_down_sync(0xffffffffu, g2,    off);
        h2    += __shfl_down_sync(0xffffffffu, h2,    off);
    }

    __shared__ float s_d[THREADS / 32];
    __shared__ float s_g[THREADS / 32];
    __shared__ float s_h[THREADS / 32];
    int lane = threadIdx.x & 31;
    int wid  = threadIdx.x >> 5;
    if (lane == 0) { s_d[wid] = diff2; s_g[wid] = g2; s_h[wid] = h2; }
    __syncthreads();

    if (wid == 0) {
        float d  = (lane < THREADS / 32) ? s_d[lane] : 0.f;
        float gg = (lane < THREADS / 32) ? s_g[lane] : 0.f;
        float hh = (lane < THREADS / 32) ? s_h[lane] : 0.f;
        #pragma unroll
        for (int off = 4; off > 0; off >>= 1) {
            d  += __shfl_down_sync(0xffffffffu, d,  off);
            gg += __shfl_down_sync(0xffffffffu, gg, off);
            hh += __shfl_down_sync(0xffffffffu, hh, off);
        }
        if (lane == 0) {
            atomicAdd(&g_acc[0], (double)d);
            atomicAdd(&g_acc[1], (double)gg);
            atomicAdd(&g_acc[2], (double)hh);
            __threadfence();
            unsigned int prev = atomicAdd(&g_done_count, 1u);
            if (prev == NBLOCKS - 1) {
                // Last block: all adds globally visible. Read via atomic path
                // (L2) to avoid stale L1, finalize, reset for next replay.
                double diff2_t = atomicAdd(&g_acc[0], 0.0);
                double g2_t    = atomicAdd(&g_acc[1], 0.0);
                double h2_t    = atomicAdd(&g_acc[2], 0.0);
                out[0] = (float)(diff2_t / g2_t + (double)LAMBDA_F * (diff2_t / h2_t));
                g_acc[0] = 0.0;
                g_acc[1] = 0.0;
                g_acc[2] = 0.0;
                __threadfence();
                g_done_count = 0u;
            }
        }
    }
}

extern "C" void kernel_launch(void* const* d_in, const int* in_sizes, int n_in,
                              void* d_out, int out_size) {
    const float4* est = (const float4*)d_in[0];
    const float4* gt  = (const float4*)d_in[1];
    float* out = (float*)d_out;

    pra_fused_kernel<<<NBLOCKS, THREADS>>>(est, gt, out);
}

// round 9
// speedup vs baseline: 1.0942x; 1.0409x over previous
#include <cuda_runtime.h>
#include <cuda_bf16.h>

// Problem constants (fixed by reference setup_inputs)
#define B_DIM 32
#define HW (1024 * 1024)
#define VEC (HW / 4)          // float4 pixels per image
#define THREADS 256
#define NBLOCKS (VEC / THREADS)   // 1024
#define GROUP 4                   // b-slices batched per load group
#define LAMBDA_F 0.1f

// Global accumulators: [0]=diff2, [1]=G2, [2]=H2. Zero-initialized at module
// load; the finalizing block resets them, so each graph replay starts clean.
__device__ double g_acc[3];
__device__ unsigned int g_done_count;

__global__ __launch_bounds__(THREADS, 4) void pra_fused_kernel(
    const float4* __restrict__ est, const float4* __restrict__ gt,
    float* __restrict__ out)
{
    int p = blockIdx.x * THREADS + threadIdx.x;   // vec-pixel index, p < VEC

    float4 se = make_float4(0.f, 0.f, 0.f, 0.f);  // per-pixel batch sum of est
    float4 sg = make_float4(0.f, 0.f, 0.f, 0.f);  // per-pixel batch sum of gt
    float4 e2 = make_float4(0.f, 0.f, 0.f, 0.f);  // per-pixel sum of est^2
    float diff2 = 0.f;

    // Front-batch GROUP b-slices of loads before consuming any of them
    // (R6 optimum: 8 independent LDG.128 per thread per group -> deep MLP),
    // with .cs evict-first policy: the data is strictly read-once, so don't
    // let it churn L2.
    for (int b0 = 0; b0 < B_DIM; b0 += GROUP) {
        float4 eb[GROUP], gb[GROUP];
        #pragma unroll
        for (int j = 0; j < GROUP; j++)
            eb[j] = __ldcs(&est[(size_t)(b0 + j) * VEC + p]);
        #pragma unroll
        for (int j = 0; j < GROUP; j++)
            gb[j] = __ldcs(&gt[(size_t)(b0 + j) * VEC + p]);

        #pragma unroll
        for (int j = 0; j < GROUP; j++) {
            float4 e = eb[j], g = gb[j];
            se.x += e.x; se.y += e.y; se.z += e.z; se.w += e.w;
            sg.x += g.x; sg.y += g.y; sg.z += g.z; sg.w += g.w;
            e2.x = fmaf(e.x, e.x, e2.x);
            e2.y = fmaf(e.y, e.y, e2.y);
            e2.z = fmaf(e.z, e.z, e2.z);
            e2.w = fmaf(e.w, e.w, e2.w);
            float dx = e.x - g.x, dy = e.y - g.y, dz = e.z - g.z, dw = e.w - g.w;
            diff2 = fmaf(dx, dx, diff2);
            diff2 = fmaf(dy, dy, diff2);
            diff2 = fmaf(dz, dz, diff2);
            diff2 = fmaf(dw, dw, diff2);
        }
    }

    float g2 = e2.x + e2.y + e2.z + e2.w;
    float h2 = (se.x > sg.x ? e2.x : 0.f)
             + (se.y > sg.y ? e2.y : 0.f)
             + (se.z > sg.z ? e2.z : 0.f)
             + (se.w > sg.w ? e2.w : 0.f);

    // ---- block reduction: warp shuffle then shared ----
    #pragma unroll
    for (int off = 16; off > 0; off >>= 1) {
        diff2 += __shfl_down_sync(0xffffffffu, diff2, off);
        g2    += __shfl_down_sync(0xffffffffu, g2,    off);
        h2    += __shfl_down_sync(0xffffffffu, h2,    off);
    }

    __shared__ float s_d[THREADS / 32];
    __shared__ float s_g[THREADS / 32];
    __shared__ float s_h[THREADS / 32];
    int lane = threadIdx.x & 31;
    int wid  = threadIdx.x >> 5;
    if (lane == 0) { s_d[wid] = diff2; s_g[wid] = g2; s_h[wid] = h2; }
    __syncthreads();

    if (wid == 0) {
        float d  = (lane < THREADS / 32) ? s_d[lane] : 0.f;
        float gg = (lane < THREADS / 32) ? s_g[lane] : 0.f;
        float hh = (lane < THREADS / 32) ? s_h[lane] : 0.f;
        #pragma unroll
        for (int off = 4; off > 0; off >>= 1) {
            d  += __shfl_down_sync(0xffffffffu, d,  off);
            gg += __shfl_down_sync(0xffffffffu, gg, off);
            hh += __shfl_down_sync(0xffffffffu, hh, off);
        }
        if (lane == 0) {
            atomicAdd(&g_acc[0], (double)d);
            atomicAdd(&g_acc[1], (double)gg);
            atomicAdd(&g_acc[2], (double)hh);
            __threadfence();
            unsigned int prev = atomicAdd(&g_done_count, 1u);
            if (prev == NBLOCKS - 1) {
                // Last block: all adds globally visible. Read via atomic path
                // (L2) to avoid stale L1, finalize, reset for next replay.
                double diff2_t = atomicAdd(&g_acc[0], 0.0);
                double g2_t    = atomicAdd(&g_acc[1], 0.0);
                double h2_t    = atomicAdd(&g_acc[2], 0.0);
                out[0] = (float)(diff2_t / g2_t + (double)LAMBDA_F * (diff2_t / h2_t));
                g_acc[0] = 0.0;
                g_acc[1] = 0.0;
                g_acc[2] = 0.0;
                __threadfence();
                g_done_count = 0u;
            }
        }
    }
}

extern "C" void kernel_launch(void* const* d_in, const int* in_sizes, int n_in,
                              void* d_out, int out_size) {
    const float4* est = (const float4*)d_in[0];
    const float4* gt  = (const float4*)d_in[1];
    float* out = (float*)d_out;

    pra_fused_kernel<<<NBLOCKS, THREADS>>>(est, gt, out);
}